// round 5
// baseline (speedup 1.0000x reference)
#include <cuda_runtime.h>
#include <cuda_bf16.h>
#include <cstdint>

#define GIBS   32      // 4 kinds * G=8
#define OBS    16
#define KSUP   32
#define MAX_N  100000
#define MAX_M  50000
#define QPW    4       // queries per warp (batched phase A for MLP)

// Scratch (static __device__ globals; no runtime allocation)
__device__ float4 g_pts4[MAX_N];
__device__ float4 g_q4[MAX_M];
__device__ float4 g_coefB[GIBS];   // (Bx,By,Bz,Bw) per GIB, -0.5*log2(e) folded

// ---------------------------------------------------------------------------
// Prep: pack points & queries into float4; fold all 4 GIB kinds into one
// quadratic form  arg = Bx*x^2 + By*y^2 + Bz*z^2 + Bw*(z*r_xy)
// so the per-(neighbor,GIB) cost is 4 FMA + 1 ex2.approx.
// ---------------------------------------------------------------------------
__global__ void prep_kernel(const float* __restrict__ pts, int n,
                            const float* __restrict__ qcs, int m,
                            const float* __restrict__ cy_r,
                            const float* __restrict__ dk_r,
                            const float* __restrict__ dk_w,
                            const float* __restrict__ cn_r,
                            const float* __restrict__ cn_i,
                            const float* __restrict__ el_r) {
    int i = blockIdx.x * blockDim.x + threadIdx.x;
    if (i < n) g_pts4[i] = make_float4(pts[3*i], pts[3*i+1], pts[3*i+2], 0.f);
    if (i < m) g_q4[i]   = make_float4(qcs[3*i], qcs[3*i+1], qcs[3*i+2], 0.f);
    if (i < GIBS) {
        const float NL  = -0.72134752044448170f;  // -0.5 * log2(e)
        const float EPS = 1e-8f;
        int kind = i >> 3, gi = i & 7;
        float Bx = 0.f, By = 0.f, Bz = 0.f, Bw = 0.f;
        if (kind == 0) {                       // cylinder
            float r = cy_r[gi]; float a = NL / (r*r + EPS);
            Bx = a; By = a;
        } else if (kind == 1) {                // cone
            float r = cn_r[gi], inc = cn_i[gi];
            float c = NL / (r*r + EPS);
            Bx = c; By = c; Bz = c * inc * inc; Bw = -2.f * c * inc;
        } else if (kind == 2) {                // disk
            float r = dk_r[gi], w = dk_w[gi];
            float a = NL / (r*r + EPS);
            Bx = a; By = a; Bz = NL / (w*w + EPS);
        } else {                               // ellipsoid
            float rx = el_r[gi*3+0], ry = el_r[gi*3+1], rz = el_r[gi*3+2];
            Bx = NL / (rx*rx + EPS); By = NL / (ry*ry + EPS); Bz = NL / (rz*rz + EPS);
        }
        g_coefB[i] = make_float4(Bx, By, Bz, Bw);
    }
}

// ---------------------------------------------------------------------------
// Main: warp per QPW queries.
//  Phase A (BATCHED): all QPW queries' index loads + point gathers issued
//    back-to-back (MLP=QPW) -> masks -> ballot-compact features into shared.
//  Phase B (lane=GIB): per query, loop over ~8% survivors: LDS.128+4FMA+ex2.
//  Epilogue: register lambdas; 16 shfl + 16 FMA + xor16 per query.
// ---------------------------------------------------------------------------
__global__ __launch_bounds__(256)
void gib_main_kernel(const int*   __restrict__ sidx,
                     const float* __restrict__ lambdas,
                     float*       __restrict__ out,
                     int m_total) {
    __shared__ float4 shF[8][QPW][32];   // 16KB

    int tid  = threadIdx.x;
    int w    = tid >> 5;
    int lane = tid & 31;
    int o    = lane & 15;
    int half = lane >> 4;

    // per-lane GIB coefficients (one LDG.128, L2-resident)
    float4 B = g_coefB[lane];

    // lambda column for this lane's (half, o): 16 registers, loaded once
    float lamr[16];
    #pragma unroll
    for (int g = 0; g < 16; ++g)
        lamr[g] = __ldg(&lambdas[((half << 4) + g) * OBS + o]);

    int m0 = (blockIdx.x * 8 + w) * QPW;

    // ---- Phase A batched: issue ALL gathers first (high MLP) ----
    int mq[QPW];
    int idxs[QPW];
    #pragma unroll
    for (int qi = 0; qi < QPW; ++qi) {
        int m = m0 + qi;
        mq[qi] = m < m_total ? m : (m_total - 1);    // clamp (safe loads)
        idxs[qi] = sidx[mq[qi] * KSUP + lane];       // coalesced
    }
    float4 pv[QPW];
    float4 qv[QPW];
    #pragma unroll
    for (int qi = 0; qi < QPW; ++qi) {
        pv[qi] = g_pts4[idxs[qi]];                   // 4 gathers in flight
        qv[qi] = g_q4[mq[qi]];                       // uniform broadcasts
    }

    int cnt[QPW];
    #pragma unroll
    for (int qi = 0; qi < QPW; ++qi) {
        float rx = pv[qi].x - qv[qi].x;
        float ry = pv[qi].y - qv[qi].y;
        float rz = pv[qi].z - qv[qi].z;
        float x2 = rx*rx, y2 = ry*ry, z2 = rz*rz;
        float xy2 = x2 + y2;
        bool pred = (xy2 + z2 <= 1.0f);              // REACH^2
        unsigned bal = __ballot_sync(0xffffffffu, pred);
        cnt[qi] = __popc(bal);
        if (pred) {
            float rxy;
            asm("sqrt.approx.f32 %0, %1;" : "=f"(rxy) : "f"(xy2 + 1e-8f));
            int rank = __popc(bal & ((1u << lane) - 1u));
            shF[w][qi][rank] = make_float4(x2, y2, z2, rz * rxy);
        }
    }
    __syncwarp();

    // ---- Phase B + epilogue per query ----
    #pragma unroll 1
    for (int qi = 0; qi < QPW; ++qi) {
        float acc = 0.f;
        int c = cnt[qi];
        for (int j = 0; j < c; ++j) {
            float4 f = shF[w][qi][j];                // LDS.128 broadcast
            float arg = fmaf(f.x, B.x,
                        fmaf(f.y, B.y,
                        fmaf(f.z, B.z, f.w * B.w)));
            float wv;
            asm("ex2.approx.f32 %0, %1;" : "=f"(wv) : "f"(arg));
            acc += wv;
        }

        float s = 0.f;
        #pragma unroll
        for (int g = 0; g < 16; ++g) {
            float a = __shfl_sync(0xffffffffu, acc, (half << 4) + g);
            s = fmaf(a, lamr[g], s);
        }
        s += __shfl_xor_sync(0xffffffffu, s, 16);
        if (lane < 16 && (m0 + qi) < m_total)
            out[(m0 + qi) * OBS + lane] = s * (1.0f / (float)KSUP);
    }
}

// ---------------------------------------------------------------------------
extern "C" void kernel_launch(void* const* d_in, const int* in_sizes, int n_in,
                              void* d_out, int out_size) {
    const float* points = (const float*)d_in[0];
    const float* qc     = (const float*)d_in[1];
    const int*   sidx   = (const int*)  d_in[2];
    const float* cy_r   = (const float*)d_in[3];
    const float* dk_r   = (const float*)d_in[4];
    const float* dk_w   = (const float*)d_in[5];
    const float* cn_r   = (const float*)d_in[6];
    const float* cn_i   = (const float*)d_in[7];
    const float* el_r   = (const float*)d_in[8];
    const float* lam    = (const float*)d_in[9];
    float* out = (float*)d_out;

    int n = in_sizes[0] / 3;   // 100000
    int m = in_sizes[1] / 3;   // 50000

    int pmax = n > m ? n : m;
    prep_kernel<<<(pmax + 255) / 256, 256>>>(points, n, qc, m,
                                             cy_r, dk_r, dk_w, cn_r, cn_i, el_r);

    int queries_per_block = 8 * QPW;
    gib_main_kernel<<<(m + queries_per_block - 1) / queries_per_block, 256>>>(
        sidx, lam, out, m);
}

// round 6
// speedup vs baseline: 1.0312x; 1.0312x over previous
#include <cuda_runtime.h>
#include <cuda_bf16.h>
#include <cstdint>

#define GIBS   32      // 4 kinds * G=8
#define OBS    16
#define KSUP   32
#define MAX_N  100000
#define MAX_M  50000
#define QPW    8       // queries per warp (serial, with depth-1 prefetch)

// Scratch (static __device__ globals; no runtime allocation)
__device__ float4 g_pts4[MAX_N];
__device__ float4 g_q4[MAX_M];
__device__ float4 g_coefB[GIBS];   // (Bx,By,Bz,Bw) per GIB, -0.5*log2(e) folded

// ---------------------------------------------------------------------------
// Prep: pack points & queries into float4; fold all 4 GIB kinds into one
// quadratic form  arg = Bx*x^2 + By*y^2 + Bz*z^2 + Bw*(z*r_xy)
// so the per-(neighbor,GIB) cost is 4 FMA + 1 ex2.approx.
// ---------------------------------------------------------------------------
__global__ void prep_kernel(const float* __restrict__ pts, int n,
                            const float* __restrict__ qcs, int m,
                            const float* __restrict__ cy_r,
                            const float* __restrict__ dk_r,
                            const float* __restrict__ dk_w,
                            const float* __restrict__ cn_r,
                            const float* __restrict__ cn_i,
                            const float* __restrict__ el_r) {
    int i = blockIdx.x * blockDim.x + threadIdx.x;
    if (i < n) g_pts4[i] = make_float4(pts[3*i], pts[3*i+1], pts[3*i+2], 0.f);
    if (i < m) g_q4[i]   = make_float4(qcs[3*i], qcs[3*i+1], qcs[3*i+2], 0.f);
    if (i < GIBS) {
        const float NL  = -0.72134752044448170f;  // -0.5 * log2(e)
        const float EPS = 1e-8f;
        int kind = i >> 3, gi = i & 7;
        float Bx = 0.f, By = 0.f, Bz = 0.f, Bw = 0.f;
        if (kind == 0) {                       // cylinder
            float r = cy_r[gi]; float a = NL / (r*r + EPS);
            Bx = a; By = a;
        } else if (kind == 1) {                // cone
            float r = cn_r[gi], inc = cn_i[gi];
            float c = NL / (r*r + EPS);
            Bx = c; By = c; Bz = c * inc * inc; Bw = -2.f * c * inc;
        } else if (kind == 2) {                // disk
            float r = dk_r[gi], w = dk_w[gi];
            float a = NL / (r*r + EPS);
            Bx = a; By = a; Bz = NL / (w*w + EPS);
        } else {                               // ellipsoid
            float rx = el_r[gi*3+0], ry = el_r[gi*3+1], rz = el_r[gi*3+2];
            Bx = NL / (rx*rx + EPS); By = NL / (ry*ry + EPS); Bz = NL / (rz*rz + EPS);
        }
        g_coefB[i] = make_float4(Bx, By, Bz, Bw);
    }
}

// ---------------------------------------------------------------------------
// Main: warp per QPW queries (serial loop, depth-1 gather prefetch).
//  Phase A (lane=neighbor): gather, reach mask, BRANCHLESS predicated
//                           compact-store of features f=(x2,y2,z2,z*rxy).
//  Phase B (lane=GIB):      ~8% survivors: LDS.128 + 4 FMA + ex2 each.
//  Epilogue:                STS acc + 4x LDS.128 broadcast + 16 FMA + xor16
//                           (replaces 16 gather-SHFLs -> far fewer MIO ops).
// ---------------------------------------------------------------------------
__global__ __launch_bounds__(256)
void gib_main_kernel(const int*   __restrict__ sidx,
                     const float* __restrict__ lambdas,
                     float*       __restrict__ out,
                     int m_total) {
    __shared__ float4 shF[8][32];    // 4KB  compacted features per warp
    __shared__ float  accS[8][32];   // 1KB  acc staging per warp

    int tid  = threadIdx.x;
    int w    = tid >> 5;
    int lane = tid & 31;
    int o    = lane & 15;
    int half = lane >> 4;

    // per-lane GIB coefficients (one LDG.128, L2-resident)
    float4 B = g_coefB[lane];

    // lambda column for this lane's (half, o): 16 registers, loaded once
    float lamr[16];
    #pragma unroll
    for (int g = 0; g < 16; ++g)
        lamr[g] = __ldg(&lambdas[((half << 4) + g) * OBS + o]);

    int m0 = (blockIdx.x * 8 + w) * QPW;
    if (m0 >= m_total) return;
    int mend = m_total - m0; if (mend > QPW) mend = QPW;

    // prefetch first query's data
    int    idx = sidx[m0 * KSUP + lane];
    float4 p   = g_pts4[idx];
    float4 q   = g_q4[m0];

    #pragma unroll 1
    for (int qi = 0; qi < mend; ++qi) {
        // ---- Phase A (branchless) ----
        float rx = p.x - q.x, ry = p.y - q.y, rz = p.z - q.z;
        float x2 = rx*rx, y2 = ry*ry, z2 = rz*rz;
        float xy2 = x2 + y2;
        bool pred = (xy2 + z2 <= 1.0f);             // REACH^2
        unsigned bal = __ballot_sync(0xffffffffu, pred);
        int cnt  = __popc(bal);
        int rank = __popc(bal & ((1u << lane) - 1u));
        float rxy;
        asm("sqrt.approx.f32 %0, %1;" : "=f"(rxy) : "f"(xy2 + 1e-8f));
        float zr = rz * rxy;

        // predicated compact store (no branch, no BSSY)
        unsigned saddr = (unsigned)__cvta_generic_to_shared(&shF[w][rank]);
        asm volatile(
            "{ .reg .pred p; setp.ne.u32 p, %0, 0;"
            "  @p st.shared.v4.f32 [%1], {%2, %3, %4, %5}; }"
            :: "r"((unsigned)pred), "r"(saddr),
               "f"(x2), "f"(y2), "f"(z2), "f"(zr));

        // ---- depth-1 prefetch of next query (overlaps phase B latency) ----
        int mn = m0 + qi + 1; mn = mn < m_total ? mn : (m_total - 1);
        int idxn = sidx[mn * KSUP + lane];
        float4 pn = g_pts4[idxn];
        float4 qn = g_q4[mn];

        __syncwarp();                                // shF visible warp-wide

        // ---- Phase B: lane = GIB ----
        float acc = 0.f;
        for (int j = 0; j < cnt; ++j) {
            float4 f = shF[w][j];                    // LDS.128 broadcast
            float arg = fmaf(f.x, B.x,
                        fmaf(f.y, B.y,
                        fmaf(f.z, B.z, f.w * B.w)));
            float wv;
            asm("ex2.approx.f32 %0, %1;" : "=f"(wv) : "f"(arg));
            acc += wv;
        }

        // ---- Epilogue via shared broadcast (6 MIO ops vs 17 shfl) ----
        accS[w][lane] = acc;
        __syncwarp();
        float s = 0.f;
        #pragma unroll
        for (int j = 0; j < 4; ++j) {
            float4 a4 = *reinterpret_cast<const float4*>(&accS[w][(half << 4) + 4*j]);
            s = fmaf(a4.x, lamr[4*j+0],
                fmaf(a4.y, lamr[4*j+1],
                fmaf(a4.z, lamr[4*j+2],
                fmaf(a4.w, lamr[4*j+3], s))));
        }
        s += __shfl_xor_sync(0xffffffffu, s, 16);
        if (lane < 16)
            out[(m0 + qi) * OBS + lane] = s * (1.0f / (float)KSUP);

        p = pn; q = qn;
    }
}

// ---------------------------------------------------------------------------
extern "C" void kernel_launch(void* const* d_in, const int* in_sizes, int n_in,
                              void* d_out, int out_size) {
    const float* points = (const float*)d_in[0];
    const float* qc     = (const float*)d_in[1];
    const int*   sidx   = (const int*)  d_in[2];
    const float* cy_r   = (const float*)d_in[3];
    const float* dk_r   = (const float*)d_in[4];
    const float* dk_w   = (const float*)d_in[5];
    const float* cn_r   = (const float*)d_in[6];
    const float* cn_i   = (const float*)d_in[7];
    const float* el_r   = (const float*)d_in[8];
    const float* lam    = (const float*)d_in[9];
    float* out = (float*)d_out;

    int n = in_sizes[0] / 3;   // 100000
    int m = in_sizes[1] / 3;   // 50000

    int pmax = n > m ? n : m;
    prep_kernel<<<(pmax + 255) / 256, 256>>>(points, n, qc, m,
                                             cy_r, dk_r, dk_w, cn_r, cn_i, el_r);

    int queries_per_block = 8 * QPW;                 // 64
    gib_main_kernel<<<(m + queries_per_block - 1) / queries_per_block, 256>>>(
        sidx, lam, out, m);
}